// round 17
// baseline (speedup 1.0000x reference)
#include <cuda_runtime.h>
#include <cstdint>

#define NN 100000
#define NE 1600000
#define HD 64
#define NL 3
#define NGR 1000
#define RB 32                          // rows per block (gemm-class)
#define GB (NN / RB)                   // 3125 blocks, exact

// ---------------- device scratch (allocation-free) ----------------
__device__ float g_h[(size_t)NN * HD];            // post-BN node features
__device__ float g_t[(size_t)NN * HD];            // y1 intermediate
__device__ float g_yl[NL][(size_t)NN * HD];       // y2 (pre-BN) per layer
__device__ float g_agg[(size_t)NN * HD];
__device__ float g_gate[NN];
__device__ float g_e[NN];
__device__ float g_sc1[HD], g_sh1[HD];
__device__ float g_scL[NL][HD], g_shL[NL][HD];
__device__ float g_bnsum[HD];
__device__ float g_bnsq[HD];
__device__ unsigned g_segmax[NGR];
__device__ float g_denom[NGR];

// ---------------- helpers ----------------
__device__ __forceinline__ unsigned encf(float f) {
    unsigned u = __float_as_uint(f);
    return (u & 0x80000000u) ? ~u : (u | 0x80000000u);
}
__device__ __forceinline__ float decf(unsigned e) {
    return __uint_as_float((e & 0x80000000u) ? (e & 0x7FFFFFFFu) : ~e);
}
__device__ __forceinline__ void red_add_v4(float* p, float4 v) {
    asm volatile("red.global.add.v4.f32 [%0], {%1,%2,%3,%4};"
                 :: "l"(p), "f"(v.x), "f"(v.y), "f"(v.z), "f"(v.w) : "memory");
}
__device__ __forceinline__ float4 bnrelu4(float4 y, float4 sc, float4 sh) {
    return make_float4(fmaxf(fmaf(y.x, sc.x, sh.x), 0.f),
                       fmaxf(fmaf(y.y, sc.y, sh.y), 0.f),
                       fmaxf(fmaf(y.z, sc.z, sh.z), 0.f),
                       fmaxf(fmaf(y.w, sc.w, sh.w), 0.f));
}

// ---------------- zero / finalize kernels ----------------
__global__ void fin_zero_k(int l) {
    int gid = blockIdx.x * blockDim.x + threadIdx.x;
    if (gid >= NN * 16) return;
    int i = gid >> 4;
    int j = (gid & 15) << 2;
    *(float4*)(g_agg + (size_t)i * HD + j) = make_float4(0.f, 0.f, 0.f, 0.f);
    if (l > 0) {
        float4 y = *(const float4*)(g_yl[l - 1] + (size_t)i * HD + j);
        float4 v = bnrelu4(y, *(const float4*)(g_scL[l - 1] + j),
                              *(const float4*)(g_shL[l - 1] + j));
        *(float4*)(g_h + (size_t)i * HD + j) = v;
    }
}
__global__ void zero_misc_k(float* pooled) {
    int i = blockIdx.x * blockDim.x + threadIdx.x;
    if (i < NGR) { g_denom[i] = 0.f; g_segmax[i] = 0u; }
    if (i < HD) { g_bnsum[i] = 0.f; g_bnsq[i] = 0.f; }
    if (i < NGR * HD / 4)
        ((float4*)pooled)[i] = make_float4(0.f, 0.f, 0.f, 0.f);
}

// ---------------- edge scatter: agg[dst] += h[src] ----------------
__global__ void scatter_k(const float* __restrict__ x, const int* __restrict__ ei, int l) {
    const float* __restrict__ h = (l == 0) ? x : g_h;
    int gid = blockIdx.x * blockDim.x + threadIdx.x;
    if (gid >= NE * 8) return;
    int e = gid >> 3;
    int j = (gid & 7) << 3;
    int src = ei[e];
    int dst = ei[NE + e];
    const float* hp = h + (size_t)src * HD + j;
    float4 v0 = *(const float4*)(hp);
    float4 v1 = *(const float4*)(hp + 4);
    float* ap = g_agg + (size_t)dst * HD + j;
    red_add_v4(ap, v0);
    red_add_v4(ap + 4, v1);
}

// ---------------- GEMM: one row per thread, B broadcast from smem ----------------
// MODE 0: z = (1+eps[l])*h + agg, h = x (l==0) or g_h;   y -> g_t
// MODE 1: z = relu(bn1(g_t));                             y -> g_yl[l]
// Block: 256 threads = 32 rows (lane) x 8 col-groups (warp). NN % 32 == 0.
template <int MODE>
__global__ __launch_bounds__(256, 6) void gemm_bn_k(const float* __restrict__ Ax,
                                                    const float* __restrict__ W,
                                                    const float* __restrict__ bias,
                                                    const float* __restrict__ epsv, int l) {
    __shared__ __align__(16) float Bs[HD * HD];     // [k][n] 16KB
    __shared__ __align__(16) float s_sc[HD], s_sh[HD];
    const int t = threadIdx.x;
    const int lane = t & 31;
    const int nb = (t >> 5) * 8;
    const int m = blockIdx.x * RB + lane;

    for (int i = t; i < HD * HD; i += 256) Bs[i] = W[i];
    if (MODE == 1 && t < HD) { s_sc[t] = g_sc1[t]; s_sh[t] = g_sh1[t]; }
    __syncthreads();

    const float* __restrict__ Arow =
        ((MODE == 0) ? ((l == 0) ? Ax : (const float*)g_h) : (const float*)g_t) + (size_t)m * HD;
    const float* __restrict__ aggrow = g_agg + (size_t)m * HD;
    float ep = (MODE == 0) ? (1.0f + epsv[l]) : 0.f;

    float acc[8];
#pragma unroll
    for (int c = 0; c < 8; c++) acc[c] = 0.f;

#pragma unroll 4
    for (int k0 = 0; k0 < HD; k0 += 4) {
        float4 a = *(const float4*)(Arow + k0);
        if (MODE == 0) {
            float4 g = *(const float4*)(aggrow + k0);
            a = make_float4(fmaf(ep, a.x, g.x), fmaf(ep, a.y, g.y),
                            fmaf(ep, a.z, g.z), fmaf(ep, a.w, g.w));
        } else {
            a = bnrelu4(a, *(const float4*)(s_sc + k0), *(const float4*)(s_sh + k0));
        }
        float av[4] = {a.x, a.y, a.z, a.w};
#pragma unroll
        for (int i = 0; i < 4; i++) {
            float4 b0 = *(const float4*)(Bs + (k0 + i) * HD + nb);
            float4 b1 = *(const float4*)(Bs + (k0 + i) * HD + nb + 4);
            acc[0] = fmaf(av[i], b0.x, acc[0]);
            acc[1] = fmaf(av[i], b0.y, acc[1]);
            acc[2] = fmaf(av[i], b0.z, acc[2]);
            acc[3] = fmaf(av[i], b0.w, acc[3]);
            acc[4] = fmaf(av[i], b1.x, acc[4]);
            acc[5] = fmaf(av[i], b1.y, acc[5]);
            acc[6] = fmaf(av[i], b1.z, acc[6]);
            acc[7] = fmaf(av[i], b1.w, acc[7]);
        }
    }

#pragma unroll
    for (int c = 0; c < 8; c++) acc[c] += bias[nb + c];

    float* ybuf = (MODE == 0) ? g_t : g_yl[l];
    *(float4*)(ybuf + (size_t)m * HD + nb) = make_float4(acc[0], acc[1], acc[2], acc[3]);
    *(float4*)(ybuf + (size_t)m * HD + nb + 4) = make_float4(acc[4], acc[5], acc[6], acc[7]);

    // column stats: shuffle-reduce over the warp's 32 rows
#pragma unroll
    for (int c = 0; c < 8; c++) {
        float ps = acc[c];
        float pq = acc[c] * acc[c];
#pragma unroll
        for (int off = 16; off > 0; off >>= 1) {
            ps += __shfl_xor_sync(0xffffffffu, ps, off);
            pq += __shfl_xor_sync(0xffffffffu, pq, off);
        }
        if (lane == 0) {
            atomicAdd(&g_bnsum[nb + c], ps);
            atomicAdd(&g_bnsq[nb + c], pq);
        }
    }
}

// ---------------- BN finalize ----------------
__global__ void statfin_k(const float* __restrict__ gamma, const float* __restrict__ beta,
                          int mode, int l) {
    int n = threadIdx.x;
    if (n < HD) {
        const float inv = 1.0f / (float)NN;
        float mean = g_bnsum[n] * inv;
        float var = g_bnsq[n] * inv - mean * mean;
        float s = gamma[n] * rsqrtf(var + 1e-5f);
        float sh = fmaf(-mean, s, beta[n]);
        if (mode == 0) { g_sc1[n] = s; g_sh1[n] = sh; }
        else           { g_scL[l][n] = s; g_shL[l][n] = sh; }
        g_bnsum[n] = 0.f;
        g_bnsq[n] = 0.f;
    }
}

// ---------------- lin+gate: one row per thread, 3 k-chunks ----------------
__global__ __launch_bounds__(256, 6) void lin_gate_k(const float* __restrict__ lw,
                                                     const float* __restrict__ lb,
                                                     const float* __restrict__ gw,
                                                     const float* __restrict__ gb,
                                                     const int* __restrict__ batch,
                                                     float* __restrict__ hh) {
    __shared__ __align__(16) float Bs[HD * HD];
    __shared__ __align__(16) float s_sc[HD], s_sh[HD];
    __shared__ float sg[RB];
    const int t = threadIdx.x;
    const int lane = t & 31;
    const int nb = (t >> 5) * 8;
    const int m = blockIdx.x * RB + lane;

    float acc[8];
#pragma unroll
    for (int c = 0; c < 8; c++) acc[c] = 0.f;

    for (int kc = 0; kc < NL; kc++) {
        __syncthreads();
        for (int i = t; i < HD * HD; i += 256) Bs[i] = lw[kc * HD * HD + i];
        if (t < HD) { s_sc[t] = g_scL[kc][t]; s_sh[t] = g_shL[kc][t]; }
        __syncthreads();

        const float* __restrict__ Arow = g_yl[kc] + (size_t)m * HD;
#pragma unroll 4
        for (int k0 = 0; k0 < HD; k0 += 4) {
            float4 a = *(const float4*)(Arow + k0);
            a = bnrelu4(a, *(const float4*)(s_sc + k0), *(const float4*)(s_sh + k0));
            float av[4] = {a.x, a.y, a.z, a.w};
#pragma unroll
            for (int i = 0; i < 4; i++) {
                float4 b0 = *(const float4*)(Bs + (k0 + i) * HD + nb);
                float4 b1 = *(const float4*)(Bs + (k0 + i) * HD + nb + 4);
                acc[0] = fmaf(av[i], b0.x, acc[0]);
                acc[1] = fmaf(av[i], b0.y, acc[1]);
                acc[2] = fmaf(av[i], b0.z, acc[2]);
                acc[3] = fmaf(av[i], b0.w, acc[3]);
                acc[4] = fmaf(av[i], b1.x, acc[4]);
                acc[5] = fmaf(av[i], b1.y, acc[5]);
                acc[6] = fmaf(av[i], b1.z, acc[6]);
                acc[7] = fmaf(av[i], b1.w, acc[7]);
            }
        }
    }

#pragma unroll
    for (int c = 0; c < 8; c++) acc[c] = fmaxf(acc[c] + lb[nb + c], 0.f);

    *(float4*)(hh + (size_t)m * HD + nb) = make_float4(acc[0], acc[1], acc[2], acc[3]);
    *(float4*)(hh + (size_t)m * HD + nb + 4) = make_float4(acc[4], acc[5], acc[6], acc[7]);

    // gate: per-row dot with gate_W, reduced across the 8 warps via smem
    if (t < RB) sg[t] = 0.f;
    __syncthreads();
    float gp = 0.f;
#pragma unroll
    for (int c = 0; c < 8; c++) gp = fmaf(acc[c], gw[nb + c], gp);
    atomicAdd(&sg[lane], gp);
    __syncthreads();
    if (t < RB) {
        int mm = blockIdx.x * RB + t;
        float gv = sg[t] + gb[0];
        g_gate[mm] = gv;
        atomicMax(&g_segmax[batch[mm]], encf(gv));
    }
}

// ---------------- softmax exp + denom ----------------
__global__ void expsum_k(const int* __restrict__ batch) {
    int i = blockIdx.x * blockDim.x + threadIdx.x;
    if (i >= NN) return;
    int b = batch[i];
    float e = expf(g_gate[i] - decf(g_segmax[b]));
    g_e[i] = e;
    atomicAdd(&g_denom[b], e);
}

// ---------------- pooled[b] += hh[i] * alpha[i] ----------------
__global__ void pool_k(const int* __restrict__ batch, const float* __restrict__ hh,
                       float* __restrict__ pooled) {
    int gid = blockIdx.x * blockDim.x + threadIdx.x;
    if (gid >= NN * 16) return;
    int i = gid >> 4;
    int j = (gid & 15) << 2;
    int b = batch[i];
    float alpha = g_e[i] / g_denom[b];
    float4 v = *(const float4*)(hh + (size_t)i * HD + j);
    red_add_v4(pooled + (size_t)b * HD + j,
               make_float4(v.x * alpha, v.y * alpha, v.z * alpha, v.w * alpha));
}

// ---------------- launch ----------------
extern "C" void kernel_launch(void* const* d_in, const int* in_sizes, int n_in,
                              void* d_out, int out_size) {
    const float* x    = (const float*)d_in[0];
    const int*   ei   = (const int*)d_in[1];
    const int*   batch= (const int*)d_in[2];
    const float* eps  = (const float*)d_in[3];
    const float* W1   = (const float*)d_in[4];
    const float* b1   = (const float*)d_in[5];
    const float* g1   = (const float*)d_in[6];
    const float* be1  = (const float*)d_in[7];
    const float* W2   = (const float*)d_in[8];
    const float* b2   = (const float*)d_in[9];
    const float* g2   = (const float*)d_in[10];
    const float* be2  = (const float*)d_in[11];
    const float* lw   = (const float*)d_in[12];
    const float* lb   = (const float*)d_in[13];
    const float* gw   = (const float*)d_in[14];
    const float* gb   = (const float*)d_in[15];

    float* out    = (float*)d_out;
    float* hh     = out;
    float* pooled = out + (size_t)NN * HD;

    zero_misc_k<<<(NGR * HD / 4 + 255) / 256, 256>>>(pooled);

    for (int l = 0; l < NL; l++) {
        fin_zero_k<<<(NN * 16 + 255) / 256, 256>>>(l);
        scatter_k<<<(NE * 8 + 255) / 256, 256>>>(x, ei, l);
        gemm_bn_k<0><<<GB, 256>>>(x, W1 + (size_t)l * HD * HD, b1 + l * HD, eps, l);
        statfin_k<<<1, 64>>>(g1 + l * HD, be1 + l * HD, 0, l);
        gemm_bn_k<1><<<GB, 256>>>(nullptr, W2 + (size_t)l * HD * HD, b2 + l * HD, eps, l);
        statfin_k<<<1, 64>>>(g2 + l * HD, be2 + l * HD, 1, l);
    }
    lin_gate_k<<<GB, 256>>>(lw, lb, gw, gb, batch, hh);
    expsum_k<<<(NN + 255) / 256, 256>>>(batch);
    pool_k<<<(NN * 16 + 255) / 256, 256>>>(batch, hh, pooled);
}